// round 15
// baseline (speedup 1.0000x reference)
#include <cuda_runtime.h>
#include <cuda_fp16.h>
#include <cstdint>

#define BB 32
#define NN 512
#define DD 256
#define NEG_INF -9e15f

// ---------------------------------------------------------------------------
// Device scratch (no allocation allowed)
// ---------------------------------------------------------------------------
__device__ float g_s[(size_t)BB * NN * NN];            // selected scores
__device__ __half g_a[(size_t)BB * NN * NN];           // alpha (fp16, unsplit)
__device__ __half g_whi[(size_t)BB * 4 * NN * DD];     // (h*a_k) hi
__device__ __half g_wlo[(size_t)BB * 4 * NN * DD];     // (h*a_k) lo
__device__ __half g_bhi[(size_t)BB * NN * DD];         // h hi
__device__ __half g_blo[(size_t)BB * NN * DD];         // h lo

// ---------------------------------------------------------------------------
// mma.sync / cp.async helpers (portable sm_80+ path; tcgen05 blocked by the
// harness's compute_103 PTX stage)
// ---------------------------------------------------------------------------
__device__ __forceinline__ uint32_t smem_to_u32(const void* p) {
    uint32_t a;
    asm("{ .reg .u64 t; cvta.to.shared.u64 t, %1; cvt.u32.u64 %0, t; }"
        : "=r"(a) : "l"(p));
    return a;
}
__device__ __forceinline__ void ldm_x4(uint32_t* r, uint32_t addr) {
    asm volatile("ldmatrix.sync.aligned.m8n8.x4.shared.b16 {%0,%1,%2,%3}, [%4];"
        : "=r"(r[0]), "=r"(r[1]), "=r"(r[2]), "=r"(r[3]) : "r"(addr));
}
__device__ __forceinline__ void ldm_x4_trans(uint32_t* r, uint32_t addr) {
    asm volatile("ldmatrix.sync.aligned.m8n8.x4.trans.shared.b16 {%0,%1,%2,%3}, [%4];"
        : "=r"(r[0]), "=r"(r[1]), "=r"(r[2]), "=r"(r[3]) : "r"(addr));
}
__device__ __forceinline__ void mma16816(float* c, const uint32_t* a, const uint32_t* b) {
    asm volatile(
        "mma.sync.aligned.m16n8k16.row.col.f32.f16.f16.f32 "
        "{%0,%1,%2,%3}, {%4,%5,%6,%7}, {%8,%9}, {%0,%1,%2,%3};"
        : "+f"(c[0]), "+f"(c[1]), "+f"(c[2]), "+f"(c[3])
        : "r"(a[0]), "r"(a[1]), "r"(a[2]), "r"(a[3]), "r"(b[0]), "r"(b[1]));
}
__device__ __forceinline__ void cp16(uint32_t dst, const void* src) {
    asm volatile("cp.async.cg.shared.global [%0], [%1], 16;" :: "r"(dst), "l"(src));
}
#define CP_COMMIT() asm volatile("cp.async.commit_group;" ::: "memory")
#define CP_WAIT0()  asm volatile("cp.async.wait_group 0;" ::: "memory")

// ---------------------------------------------------------------------------
// K0: split h and w_k = h*a_k into fp16 hi/lo planes
// ---------------------------------------------------------------------------
__device__ __forceinline__ void f16pair_store(
    __half* hi, __half* lo, float4 v)
{
    float f[4] = {v.x, v.y, v.z, v.w};
    __half hb[4], lb[4];
#pragma unroll
    for (int j = 0; j < 4; j++) {
        hb[j] = __float2half_rn(f[j]);
        lb[j] = __float2half_rn(f[j] - __half2float(hb[j]));
    }
    ((__half2*)hi)[0] = __half2(hb[0], hb[1]);
    ((__half2*)hi)[1] = __half2(hb[2], hb[3]);
    ((__half2*)lo)[0] = __half2(lb[0], lb[1]);
    ((__half2*)lo)[1] = __half2(lb[2], lb[3]);
}

__global__ __launch_bounds__(256) void k_split(
    const float* __restrict__ h,
    const float* __restrict__ a0, const float* __restrict__ a1,
    const float* __restrict__ a2, const float* __restrict__ a3)
{
    const int idx = blockIdx.x * 256 + threadIdx.x;   // [0, B*N*D/4)
    const int row = idx >> 6;
    const int c4  = idx & 63;
    const int d   = c4 * 4;
    const float4 hv = ((const float4*)h)[idx];

    {
        size_t off = (size_t)row * DD + d;
        f16pair_store(g_bhi + off, g_blo + off, hv);
    }
    const int b = row >> 9, i = row & 511;
    const float* aks[4] = {a0, a1, a2, a3};
#pragma unroll
    for (int k = 0; k < 4; k++) {
        const float4 av = ((const float4*)aks[k])[c4];
        float4 wv = make_float4(hv.x * av.x, hv.y * av.y, hv.z * av.z, hv.w * av.w);
        size_t off = (((size_t)b * 4 + k) * NN + i) * DD + d;
        f16pair_store(g_whi + off, g_wlo + off, wv);
    }
}

// ---------------------------------------------------------------------------
// K1: tensor scores (fp16 hi/lo 3-pass) with fused adj-select + leaky-relu.
// CTA = (b, head, 128i x 128j). chunk = 32, 2-stage, padded rows (R11 winner).
// Head k writes where adj==k+1; head 0 also writes NEG_INF where adj==0.
// ---------------------------------------------------------------------------
#define SAS 40                       // 32 fp16 + 8 pad
#define S_PLANE (128 * SAS)
#define S_STAGE (4 * S_PLANE)        // whi, wlo, bhi, blo
#define S_SMEM_BYTES (2 * S_STAGE * 2)

__global__ void __launch_bounds__(256, 2) k_scores_tc(const int* __restrict__ adj)
{
    extern __shared__ __half sm[];

    const int t    = threadIdx.x;
    const int w    = t >> 5;
    const int lane = t & 31;
    const int wi   = w & 3;
    const int wj   = w >> 2;
    const int b    = blockIdx.z;
    const int k    = blockIdx.y >> 2;
    const int i0   = (blockIdx.y & 3) * 128;
    const int j0   = blockIdx.x * 128;

    const uint32_t smu = smem_to_u32(sm);

    const size_t aoff = (((size_t)b * 4 + k) * NN + i0) * DD;
    const size_t boff = ((size_t)b * NN + j0) * DD;
    const __half* gA0 = g_whi + aoff;
    const __half* gA1 = g_wlo + aoff;
    const __half* gB0 = g_bhi + boff;
    const __half* gB1 = g_blo + boff;

    float acc[2][8][4];
#pragma unroll
    for (int m = 0; m < 2; m++)
#pragma unroll
        for (int n = 0; n < 8; n++)
#pragma unroll
            for (int q = 0; q < 4; q++) acc[m][n][q] = 0.f;

    const uint32_t a_row  = wi * 32 + (lane & 15);
    const uint32_t a_colb = (lane >> 4) * 8;
    const uint32_t b_row  = wj * 64 + (lane & 7) + (lane >> 4) * 8;
    const uint32_t b_colb = ((lane >> 3) & 1) * 8;

    auto load_stage = [&](int st, int d0) {
        const uint32_t s0 = smu + (uint32_t)(st * S_STAGE) * 2;
#pragma unroll
        for (int q = t; q < 512; q += 256) {
            const int r = q >> 2;
            const int c = (q & 3) * 8;
            const uint32_t so = (uint32_t)(r * SAS + c) * 2;
            const size_t go = (size_t)r * DD + d0 + c;
            cp16(s0 + 0 * S_PLANE * 2 + so, gA0 + go);
            cp16(s0 + 1 * S_PLANE * 2 + so, gA1 + go);
            cp16(s0 + 2 * S_PLANE * 2 + so, gB0 + go);
            cp16(s0 + 3 * S_PLANE * 2 + so, gB1 + go);
        }
    };

    load_stage(0, 0);
    CP_COMMIT();

    const int NCH = DD / 32;   // 8 chunks
    for (int c = 0; c < NCH; c++) {
        CP_WAIT0();
        __syncthreads();
        if (c + 1 < NCH) {
            load_stage((c + 1) & 1, (c + 1) * 32);
            CP_COMMIT();
        }

        const uint32_t s0   = smu + (uint32_t)((c & 1) * S_STAGE) * 2;
        const uint32_t sWhi = s0;
        const uint32_t sWlo = s0 + 1 * S_PLANE * 2;
        const uint32_t sBhi = s0 + 2 * S_PLANE * 2;
        const uint32_t sBlo = s0 + 3 * S_PLANE * 2;

#pragma unroll
        for (int ks = 0; ks < 2; ks++) {
            uint32_t ahi[2][4], alo[2][4];
#pragma unroll
            for (int mt = 0; mt < 2; mt++) {
                const uint32_t off = ((a_row + mt * 16) * SAS + ks * 16 + a_colb) * 2;
                ldm_x4(ahi[mt], sWhi + off);
                ldm_x4(alo[mt], sWlo + off);
            }
#pragma unroll
            for (int ntp = 0; ntp < 4; ntp++) {
                uint32_t bh[4], bl[4];
                const uint32_t off = ((b_row + ntp * 16) * SAS + ks * 16 + b_colb) * 2;
                ldm_x4(bh, sBhi + off);
                ldm_x4(bl, sBlo + off);
                // pass 1: ahi * bh
                mma16816(acc[0][ntp*2],   ahi[0], bh);
                mma16816(acc[0][ntp*2+1], ahi[0], bh + 2);
                mma16816(acc[1][ntp*2],   ahi[1], bh);
                mma16816(acc[1][ntp*2+1], ahi[1], bh + 2);
                // pass 2: ahi * bl
                mma16816(acc[0][ntp*2],   ahi[0], bl);
                mma16816(acc[0][ntp*2+1], ahi[0], bl + 2);
                mma16816(acc[1][ntp*2],   ahi[1], bl);
                mma16816(acc[1][ntp*2+1], ahi[1], bl + 2);
                // pass 3: alo * bh
                mma16816(acc[0][ntp*2],   alo[0], bh);
                mma16816(acc[0][ntp*2+1], alo[0], bh + 2);
                mma16816(acc[1][ntp*2],   alo[1], bh);
                mma16816(acc[1][ntp*2+1], alo[1], bh + 2);
            }
        }
    }

    // epilogue: predicated disjoint writes. head k owns adj==k+1; head 0
    // additionally owns adj==0 (writes NEG_INF there).
    const int g  = lane >> 2;
    const int tt = lane & 3;
    const int want = k + 1;
    float* plane    = g_s + ((size_t)b * NN + i0) * NN + j0;
    const int* adjp = adj + ((size_t)b * NN + i0) * NN + j0;
#pragma unroll
    for (int mt = 0; mt < 2; mt++) {
        const int r0 = wi * 32 + mt * 16 + g;
#pragma unroll
        for (int nt = 0; nt < 8; nt++) {
            const int c0 = wj * 64 + nt * 8 + tt * 2;
#pragma unroll
            for (int hrow = 0; hrow < 2; hrow++) {
                const size_t off = (size_t)(r0 + hrow * 8) * NN + c0;
                const int2 ad = *(const int2*)&adjp[off];
                const float v0 = acc[mt][nt][hrow * 2 + 0];
                const float v1 = acc[mt][nt][hrow * 2 + 1];
                const float o0 = (v0 > 0.f) ? v0 : 0.2f * v0;
                const float o1 = (v1 > 0.f) ? v1 : 0.2f * v1;
                if (k == 0) {
                    if (ad.x <= 1) plane[off]     = (ad.x == 1) ? o0 : NEG_INF;
                    if (ad.y <= 1) plane[off + 1] = (ad.y == 1) ? o1 : NEG_INF;
                } else {
                    if (ad.x == want) plane[off]     = o0;
                    if (ad.y == want) plane[off + 1] = o1;
                }
            }
        }
    }
}

// ---------------------------------------------------------------------------
// K2: row softmax on selected plane -> fp16 alpha
// ---------------------------------------------------------------------------
__global__ __launch_bounds__(256) void k_softmax()
{
    const int w    = threadIdx.x >> 5;
    const int lane = threadIdx.x & 31;
    const size_t row = (size_t)blockIdx.x * 8 + w;
    const float* p = g_s + row * NN;

    float v[16];
#pragma unroll
    for (int q = 0; q < 4; q++) {
        const float4 x = ((const float4*)p)[q * 32 + lane];
        v[q*4+0] = x.x; v[q*4+1] = x.y; v[q*4+2] = x.z; v[q*4+3] = x.w;
    }

    float m = v[0];
#pragma unroll
    for (int q = 1; q < 16; q++) m = fmaxf(m, v[q]);
#pragma unroll
    for (int o = 16; o > 0; o >>= 1) m = fmaxf(m, __shfl_xor_sync(0xffffffffu, m, o));

    float sum = 0.f;
#pragma unroll
    for (int q = 0; q < 16; q++) { v[q] = __expf(v[q] - m); sum += v[q]; }
#pragma unroll
    for (int o = 16; o > 0; o >>= 1) sum += __shfl_xor_sync(0xffffffffu, sum, o);

    const float inv = 1.f / sum;
    __half* ap = g_a + row * NN;
#pragma unroll
    for (int q = 0; q < 4; q++) {
        const int idx = q * 32 + lane;
        __half hb[4];
#pragma unroll
        for (int j = 0; j < 4; j++)
            hb[j] = __float2half_rn(v[q * 4 + j] * inv);
        ((__half2*)(ap + idx * 4))[0] = __half2(hb[0], hb[1]);
        ((__half2*)(ap + idx * 4))[1] = __half2(hb[2], hb[3]);
    }
}

// ---------------------------------------------------------------------------
// K3: out = alpha @ h_hi (single pass; dropped alpha*h_lo term, adds ~2.4e-4
// RMS error — within budget). 2-stage cp.async, one barrier per chunk.
// ---------------------------------------------------------------------------
#define VAS 40                         // 32 fp16 + 8 pad
#define VBS 136                        // 128 fp16 + 8 pad
#define V_APLANE (128 * VAS)
#define V_BPLANE (32 * VBS)
#define V_STAGE  (V_APLANE + V_BPLANE)
#define V_SMEM_BYTES (2 * V_STAGE * 2)

__global__ void __launch_bounds__(256, 2) k_av_tc(float* __restrict__ out)
{
    extern __shared__ __half sm[];

    const int t    = threadIdx.x;
    const int w    = t >> 5;
    const int lane = t & 31;
    const int wi   = w & 3;
    const int wj   = w >> 2;
    const int b    = blockIdx.z;
    const int i0   = blockIdx.y * 128;
    const int d0   = blockIdx.x * 128;

    const uint32_t smu = smem_to_u32(sm);

    const size_t aoff = ((size_t)b * NN + i0) * NN;
    const size_t boff = (size_t)b * NN * DD;
    const __half* gA0 = g_a + aoff;
    const __half* gB0 = g_bhi + boff;

    float acc[2][8][4];
#pragma unroll
    for (int m = 0; m < 2; m++)
#pragma unroll
        for (int n = 0; n < 8; n++)
#pragma unroll
            for (int q = 0; q < 4; q++) acc[m][n][q] = 0.f;

    const uint32_t a_row  = wi * 32 + (lane & 15);
    const uint32_t a_colb = (lane >> 4) * 8;
    const uint32_t bt_row = lane & 15;
    const uint32_t bt_col = wj * 64 + (lane >> 4) * 8;

    auto load_stage = [&](int st, int j0c) {
        const uint32_t s0 = smu + (uint32_t)(st * V_STAGE) * 2;
#pragma unroll
        for (int q = t; q < 512; q += 256) {      // A: 128 x 32 = 512 x 16B
            const int r = q >> 2;
            const int c = (q & 3) * 8;
            const uint32_t so = (uint32_t)(r * VAS + c) * 2;
            cp16(s0 + so, gA0 + (size_t)r * NN + j0c + c);
        }
#pragma unroll
        for (int q = t; q < 512; q += 256) {      // B: 32 x 128 = 512 x 16B
            const int r = q >> 4;
            const int c = (q & 15) * 8;
            const uint32_t so = (uint32_t)(r * VBS + c) * 2;
            cp16(s0 + V_APLANE * 2 + so, gB0 + (size_t)(j0c + r) * DD + d0 + c);
        }
    };

    load_stage(0, 0);
    CP_COMMIT();

    const int NCH = NN / 32;   // 16 chunks
    for (int c = 0; c < NCH; c++) {
        CP_WAIT0();
        __syncthreads();
        if (c + 1 < NCH) {
            load_stage((c + 1) & 1, (c + 1) * 32);
            CP_COMMIT();
        }

        const uint32_t s0  = smu + (uint32_t)((c & 1) * V_STAGE) * 2;
        const uint32_t sA  = s0;
        const uint32_t sB  = s0 + V_APLANE * 2;

#pragma unroll
        for (int ks = 0; ks < 2; ks++) {
            uint32_t afr[2][4];
#pragma unroll
            for (int mt = 0; mt < 2; mt++) {
                const uint32_t off = ((a_row + mt * 16) * VAS + ks * 16 + a_colb) * 2;
                ldm_x4(afr[mt], sA + off);
            }
#pragma unroll
            for (int ntp = 0; ntp < 4; ntp++) {
                uint32_t bh[4];
                const uint32_t off = ((ks * 16 + bt_row) * VBS + bt_col + ntp * 16) * 2;
                ldm_x4_trans(bh, sB + off);
                mma16816(acc[0][ntp*2],   afr[0], bh);
                mma16816(acc[0][ntp*2+1], afr[0], bh + 2);
                mma16816(acc[1][ntp*2],   afr[1], bh);
                mma16816(acc[1][ntp*2+1], afr[1], bh + 2);
            }
        }
    }

    const int g  = lane >> 2;
    const int tt = lane & 3;
    float* obase = out + ((size_t)b * NN + i0) * DD + d0;
#pragma unroll
    for (int mt = 0; mt < 2; mt++) {
        const int r0 = wi * 32 + mt * 16 + g;
#pragma unroll
        for (int nt = 0; nt < 8; nt++) {
            const int c0 = wj * 64 + nt * 8 + tt * 2;
            *(float2*)&obase[(size_t)r0 * DD + c0]       = make_float2(acc[mt][nt][0], acc[mt][nt][1]);
            *(float2*)&obase[(size_t)(r0 + 8) * DD + c0] = make_float2(acc[mt][nt][2], acc[mt][nt][3]);
        }
    }
}

// ---------------------------------------------------------------------------
extern "C" void kernel_launch(void* const* d_in, const int* in_sizes, int n_in,
                              void* d_out, int out_size)
{
    const float* hidden = (const float*)d_in[0];
    const int*   adj    = (const int*)d_in[1];
    const float* a0     = (const float*)d_in[2];
    const float* a1     = (const float*)d_in[3];
    const float* a2     = (const float*)d_in[4];
    const float* a3     = (const float*)d_in[5];
    float* out = (float*)d_out;

    cudaFuncSetAttribute(k_scores_tc,
        cudaFuncAttributeMaxDynamicSharedMemorySize, S_SMEM_BYTES);
    cudaFuncSetAttribute(k_av_tc,
        cudaFuncAttributeMaxDynamicSharedMemorySize, V_SMEM_BYTES);

    k_split<<<(BB * NN * DD / 4) / 256, 256>>>(hidden, a0, a1, a2, a3);

    dim3 g1(NN / 128, 16, BB);
    k_scores_tc<<<g1, 256, S_SMEM_BYTES>>>(adj);

    k_softmax<<<(BB * NN) / 8, 256>>>();

    dim3 g3(DD / 128, NN / 128, BB);
    k_av_tc<<<g3, 256, V_SMEM_BYTES>>>(out);
}

// round 16
// speedup vs baseline: 1.1072x; 1.1072x over previous
#include <cuda_runtime.h>
#include <cuda_fp16.h>
#include <cstdint>

#define BB 32
#define NN 512
#define DD 256
#define NEG_INF -9e15f

// ---------------------------------------------------------------------------
// Device scratch (no allocation allowed)
// ---------------------------------------------------------------------------
__device__ float g_s[(size_t)BB * NN * NN];            // selected scores (NEG_INF init)
__device__ __half g_a[(size_t)BB * NN * NN];           // alpha (fp16, unsplit)
__device__ __half g_whi[(size_t)BB * 4 * NN * DD];     // (h*a_k) hi
__device__ __half g_wlo[(size_t)BB * 4 * NN * DD];     // (h*a_k) lo
__device__ __half g_bhi[(size_t)BB * NN * DD];         // h hi
__device__ __half g_blo[(size_t)BB * NN * DD];         // h lo

// ---------------------------------------------------------------------------
// mma.sync / cp.async helpers (portable sm_80+ path; tcgen05 blocked by the
// harness's compute_103 PTX stage)
// ---------------------------------------------------------------------------
__device__ __forceinline__ uint32_t smem_to_u32(const void* p) {
    uint32_t a;
    asm("{ .reg .u64 t; cvta.to.shared.u64 t, %1; cvt.u32.u64 %0, t; }"
        : "=r"(a) : "l"(p));
    return a;
}
__device__ __forceinline__ void ldm_x4(uint32_t* r, uint32_t addr) {
    asm volatile("ldmatrix.sync.aligned.m8n8.x4.shared.b16 {%0,%1,%2,%3}, [%4];"
        : "=r"(r[0]), "=r"(r[1]), "=r"(r[2]), "=r"(r[3]) : "r"(addr));
}
__device__ __forceinline__ void ldm_x4_trans(uint32_t* r, uint32_t addr) {
    asm volatile("ldmatrix.sync.aligned.m8n8.x4.trans.shared.b16 {%0,%1,%2,%3}, [%4];"
        : "=r"(r[0]), "=r"(r[1]), "=r"(r[2]), "=r"(r[3]) : "r"(addr));
}
__device__ __forceinline__ void mma16816(float* c, const uint32_t* a, const uint32_t* b) {
    asm volatile(
        "mma.sync.aligned.m16n8k16.row.col.f32.f16.f16.f32 "
        "{%0,%1,%2,%3}, {%4,%5,%6,%7}, {%8,%9}, {%0,%1,%2,%3};"
        : "+f"(c[0]), "+f"(c[1]), "+f"(c[2]), "+f"(c[3])
        : "r"(a[0]), "r"(a[1]), "r"(a[2]), "r"(a[3]), "r"(b[0]), "r"(b[1]));
}
__device__ __forceinline__ void cp16(uint32_t dst, const void* src) {
    asm volatile("cp.async.cg.shared.global [%0], [%1], 16;" :: "r"(dst), "l"(src));
}
#define CP_COMMIT() asm volatile("cp.async.commit_group;" ::: "memory")
#define CP_WAIT0()  asm volatile("cp.async.wait_group 0;" ::: "memory")

// ---------------------------------------------------------------------------
// K0: split h and w_k = h*a_k into fp16 hi/lo planes; init g_s to NEG_INF
// ---------------------------------------------------------------------------
__device__ __forceinline__ void f16pair_store(
    __half* hi, __half* lo, float4 v)
{
    float f[4] = {v.x, v.y, v.z, v.w};
    __half hb[4], lb[4];
#pragma unroll
    for (int j = 0; j < 4; j++) {
        hb[j] = __float2half_rn(f[j]);
        lb[j] = __float2half_rn(f[j] - __half2float(hb[j]));
    }
    ((__half2*)hi)[0] = __half2(hb[0], hb[1]);
    ((__half2*)hi)[1] = __half2(hb[2], hb[3]);
    ((__half2*)lo)[0] = __half2(lb[0], lb[1]);
    ((__half2*)lo)[1] = __half2(lb[2], lb[3]);
}

__global__ __launch_bounds__(256) void k_split(
    const float* __restrict__ h,
    const float* __restrict__ a0, const float* __restrict__ a1,
    const float* __restrict__ a2, const float* __restrict__ a3)
{
    const int idx = blockIdx.x * 256 + threadIdx.x;   // [0, B*N*D/4)
    const int row = idx >> 6;
    const int c4  = idx & 63;
    const int d   = c4 * 4;
    const float4 hv = ((const float4*)h)[idx];

    // init selected-score plane to NEG_INF: 8 floats per thread covers B*N*N
    {
        const float4 n4 = make_float4(NEG_INF, NEG_INF, NEG_INF, NEG_INF);
        ((float4*)g_s)[(size_t)idx * 2]     = n4;
        ((float4*)g_s)[(size_t)idx * 2 + 1] = n4;
    }

    {
        size_t off = (size_t)row * DD + d;
        f16pair_store(g_bhi + off, g_blo + off, hv);
    }
    const int b = row >> 9, i = row & 511;
    const float* aks[4] = {a0, a1, a2, a3};
#pragma unroll
    for (int k = 0; k < 4; k++) {
        const float4 av = ((const float4*)aks[k])[c4];
        float4 wv = make_float4(hv.x * av.x, hv.y * av.y, hv.z * av.z, hv.w * av.w);
        size_t off = (((size_t)b * 4 + k) * NN + i) * DD + d;
        f16pair_store(g_whi + off, g_wlo + off, wv);
    }
}

// ---------------------------------------------------------------------------
// K1: tensor scores (fp16 hi/lo 3-pass) with fused adj-select + leaky-relu.
// CTA = (b, head, 128i x 128j). chunk = 32, 2-stage, padded rows.
// Heads write DISJOINT elements (adj==k+1) into NEG_INF-initialized g_s.
// ---------------------------------------------------------------------------
#define SAS 40                       // 32 fp16 + 8 pad
#define S_PLANE (128 * SAS)
#define S_STAGE (4 * S_PLANE)        // whi, wlo, bhi, blo
#define S_SMEM_BYTES (2 * S_STAGE * 2)

__global__ void __launch_bounds__(256, 2) k_scores_tc(const int* __restrict__ adj)
{
    extern __shared__ __half sm[];

    const int t    = threadIdx.x;
    const int w    = t >> 5;
    const int lane = t & 31;
    const int wi   = w & 3;
    const int wj   = w >> 2;
    const int b    = blockIdx.z;
    const int k    = blockIdx.y >> 2;
    const int i0   = (blockIdx.y & 3) * 128;
    const int j0   = blockIdx.x * 128;

    const uint32_t smu = smem_to_u32(sm);

    const size_t aoff = (((size_t)b * 4 + k) * NN + i0) * DD;
    const size_t boff = ((size_t)b * NN + j0) * DD;
    const __half* gA0 = g_whi + aoff;
    const __half* gA1 = g_wlo + aoff;
    const __half* gB0 = g_bhi + boff;
    const __half* gB1 = g_blo + boff;

    float acc[2][8][4];
#pragma unroll
    for (int m = 0; m < 2; m++)
#pragma unroll
        for (int n = 0; n < 8; n++)
#pragma unroll
            for (int q = 0; q < 4; q++) acc[m][n][q] = 0.f;

    const uint32_t a_row  = wi * 32 + (lane & 15);
    const uint32_t a_colb = (lane >> 4) * 8;
    const uint32_t b_row  = wj * 64 + (lane & 7) + (lane >> 4) * 8;
    const uint32_t b_colb = ((lane >> 3) & 1) * 8;

    auto load_stage = [&](int st, int d0) {
        const uint32_t s0 = smu + (uint32_t)(st * S_STAGE) * 2;
#pragma unroll
        for (int q = t; q < 512; q += 256) {
            const int r = q >> 2;
            const int c = (q & 3) * 8;
            const uint32_t so = (uint32_t)(r * SAS + c) * 2;
            const size_t go = (size_t)r * DD + d0 + c;
            cp16(s0 + 0 * S_PLANE * 2 + so, gA0 + go);
            cp16(s0 + 1 * S_PLANE * 2 + so, gA1 + go);
            cp16(s0 + 2 * S_PLANE * 2 + so, gB0 + go);
            cp16(s0 + 3 * S_PLANE * 2 + so, gB1 + go);
        }
    };

    load_stage(0, 0);
    CP_COMMIT();

    const int NCH = DD / 32;   // 8 chunks
    for (int c = 0; c < NCH; c++) {
        CP_WAIT0();
        __syncthreads();
        if (c + 1 < NCH) {
            load_stage((c + 1) & 1, (c + 1) * 32);
            CP_COMMIT();
        }

        const uint32_t s0   = smu + (uint32_t)((c & 1) * S_STAGE) * 2;
        const uint32_t sWhi = s0;
        const uint32_t sWlo = s0 + 1 * S_PLANE * 2;
        const uint32_t sBhi = s0 + 2 * S_PLANE * 2;
        const uint32_t sBlo = s0 + 3 * S_PLANE * 2;

#pragma unroll
        for (int ks = 0; ks < 2; ks++) {
            uint32_t ahi[2][4], alo[2][4];
#pragma unroll
            for (int mt = 0; mt < 2; mt++) {
                const uint32_t off = ((a_row + mt * 16) * SAS + ks * 16 + a_colb) * 2;
                ldm_x4(ahi[mt], sWhi + off);
                ldm_x4(alo[mt], sWlo + off);
            }
#pragma unroll
            for (int ntp = 0; ntp < 4; ntp++) {
                uint32_t bh[4], bl[4];
                const uint32_t off = ((b_row + ntp * 16) * SAS + ks * 16 + b_colb) * 2;
                ldm_x4(bh, sBhi + off);
                ldm_x4(bl, sBlo + off);
                // pass 1: ahi * bh
                mma16816(acc[0][ntp*2],   ahi[0], bh);
                mma16816(acc[0][ntp*2+1], ahi[0], bh + 2);
                mma16816(acc[1][ntp*2],   ahi[1], bh);
                mma16816(acc[1][ntp*2+1], ahi[1], bh + 2);
                // pass 2: ahi * bl
                mma16816(acc[0][ntp*2],   ahi[0], bl);
                mma16816(acc[0][ntp*2+1], ahi[0], bl + 2);
                mma16816(acc[1][ntp*2],   ahi[1], bl);
                mma16816(acc[1][ntp*2+1], ahi[1], bl + 2);
                // pass 3: alo * bh
                mma16816(acc[0][ntp*2],   alo[0], bh);
                mma16816(acc[0][ntp*2+1], alo[0], bh + 2);
                mma16816(acc[1][ntp*2],   alo[1], bh);
                mma16816(acc[1][ntp*2+1], alo[1], bh + 2);
            }
        }
    }

    // epilogue: predicated disjoint writes where adj == k+1 (leaky applied)
    const int g  = lane >> 2;
    const int tt = lane & 3;
    const int want = k + 1;
    float* plane    = g_s + ((size_t)b * NN + i0) * NN + j0;
    const int* adjp = adj + ((size_t)b * NN + i0) * NN + j0;
#pragma unroll
    for (int mt = 0; mt < 2; mt++) {
        const int r0 = wi * 32 + mt * 16 + g;
#pragma unroll
        for (int nt = 0; nt < 8; nt++) {
            const int c0 = wj * 64 + nt * 8 + tt * 2;
#pragma unroll
            for (int hrow = 0; hrow < 2; hrow++) {
                const size_t off = (size_t)(r0 + hrow * 8) * NN + c0;
                const int2 ad = *(const int2*)&adjp[off];
                const float v0 = acc[mt][nt][hrow * 2 + 0];
                const float v1 = acc[mt][nt][hrow * 2 + 1];
                if (ad.x == want) plane[off]     = (v0 > 0.f) ? v0 : 0.2f * v0;
                if (ad.y == want) plane[off + 1] = (v1 > 0.f) ? v1 : 0.2f * v1;
            }
        }
    }
}

// ---------------------------------------------------------------------------
// K2: row softmax on selected plane -> fp16 alpha
// ---------------------------------------------------------------------------
__global__ __launch_bounds__(256) void k_softmax()
{
    const int w    = threadIdx.x >> 5;
    const int lane = threadIdx.x & 31;
    const size_t row = (size_t)blockIdx.x * 8 + w;
    const float* p = g_s + row * NN;

    float v[16];
#pragma unroll
    for (int q = 0; q < 4; q++) {
        const float4 x = ((const float4*)p)[q * 32 + lane];
        v[q*4+0] = x.x; v[q*4+1] = x.y; v[q*4+2] = x.z; v[q*4+3] = x.w;
    }

    float m = v[0];
#pragma unroll
    for (int q = 1; q < 16; q++) m = fmaxf(m, v[q]);
#pragma unroll
    for (int o = 16; o > 0; o >>= 1) m = fmaxf(m, __shfl_xor_sync(0xffffffffu, m, o));

    float sum = 0.f;
#pragma unroll
    for (int q = 0; q < 16; q++) { v[q] = __expf(v[q] - m); sum += v[q]; }
#pragma unroll
    for (int o = 16; o > 0; o >>= 1) sum += __shfl_xor_sync(0xffffffffu, sum, o);

    const float inv = 1.f / sum;
    __half* ap = g_a + row * NN;
#pragma unroll
    for (int q = 0; q < 4; q++) {
        const int idx = q * 32 + lane;
        __half hb[4];
#pragma unroll
        for (int j = 0; j < 4; j++)
            hb[j] = __float2half_rn(v[q * 4 + j] * inv);
        ((__half2*)(ap + idx * 4))[0] = __half2(hb[0], hb[1]);
        ((__half2*)(ap + idx * 4))[1] = __half2(hb[2], hb[3]);
    }
}

// ---------------------------------------------------------------------------
// K3: out = alpha @ h_hi (single pass; dropped alpha*h_lo term, ~2.5e-4 total
// rel err — within budget). 2-stage cp.async, one barrier per chunk.
// ---------------------------------------------------------------------------
#define VAS 40                         // 32 fp16 + 8 pad
#define VBS 136                        // 128 fp16 + 8 pad
#define V_APLANE (128 * VAS)
#define V_BPLANE (32 * VBS)
#define V_STAGE  (V_APLANE + V_BPLANE)
#define V_SMEM_BYTES (2 * V_STAGE * 2)

__global__ void __launch_bounds__(256, 2) k_av_tc(float* __restrict__ out)
{
    extern __shared__ __half sm[];

    const int t    = threadIdx.x;
    const int w    = t >> 5;
    const int lane = t & 31;
    const int wi   = w & 3;
    const int wj   = w >> 2;
    const int b    = blockIdx.z;
    const int i0   = blockIdx.y * 128;
    const int d0   = blockIdx.x * 128;

    const uint32_t smu = smem_to_u32(sm);

    const size_t aoff = ((size_t)b * NN + i0) * NN;
    const size_t boff = (size_t)b * NN * DD;
    const __half* gA0 = g_a + aoff;
    const __half* gB0 = g_bhi + boff;

    float acc[2][8][4];
#pragma unroll
    for (int m = 0; m < 2; m++)
#pragma unroll
        for (int n = 0; n < 8; n++)
#pragma unroll
            for (int q = 0; q < 4; q++) acc[m][n][q] = 0.f;

    const uint32_t a_row  = wi * 32 + (lane & 15);
    const uint32_t a_colb = (lane >> 4) * 8;
    const uint32_t bt_row = lane & 15;
    const uint32_t bt_col = wj * 64 + (lane >> 4) * 8;

    auto load_stage = [&](int st, int j0c) {
        const uint32_t s0 = smu + (uint32_t)(st * V_STAGE) * 2;
#pragma unroll
        for (int q = t; q < 512; q += 256) {      // A: 128 x 32 = 512 x 16B
            const int r = q >> 2;
            const int c = (q & 3) * 8;
            const uint32_t so = (uint32_t)(r * VAS + c) * 2;
            cp16(s0 + so, gA0 + (size_t)r * NN + j0c + c);
        }
#pragma unroll
        for (int q = t; q < 512; q += 256) {      // B: 32 x 128 = 512 x 16B
            const int r = q >> 4;
            const int c = (q & 15) * 8;
            const uint32_t so = (uint32_t)(r * VBS + c) * 2;
            cp16(s0 + V_APLANE * 2 + so, gB0 + (size_t)(j0c + r) * DD + d0 + c);
        }
    };

    load_stage(0, 0);
    CP_COMMIT();

    const int NCH = NN / 32;   // 16 chunks
    for (int c = 0; c < NCH; c++) {
        CP_WAIT0();
        __syncthreads();
        if (c + 1 < NCH) {
            load_stage((c + 1) & 1, (c + 1) * 32);
            CP_COMMIT();
        }

        const uint32_t s0  = smu + (uint32_t)((c & 1) * V_STAGE) * 2;
        const uint32_t sA  = s0;
        const uint32_t sB  = s0 + V_APLANE * 2;

#pragma unroll
        for (int ks = 0; ks < 2; ks++) {
            uint32_t afr[2][4];
#pragma unroll
            for (int mt = 0; mt < 2; mt++) {
                const uint32_t off = ((a_row + mt * 16) * VAS + ks * 16 + a_colb) * 2;
                ldm_x4(afr[mt], sA + off);
            }
#pragma unroll
            for (int ntp = 0; ntp < 4; ntp++) {
                uint32_t bh[4];
                const uint32_t off = ((ks * 16 + bt_row) * VBS + bt_col + ntp * 16) * 2;
                ldm_x4_trans(bh, sB + off);
                mma16816(acc[0][ntp*2],   afr[0], bh);
                mma16816(acc[0][ntp*2+1], afr[0], bh + 2);
                mma16816(acc[1][ntp*2],   afr[1], bh);
                mma16816(acc[1][ntp*2+1], afr[1], bh + 2);
            }
        }
    }

    const int g  = lane >> 2;
    const int tt = lane & 3;
    float* obase = out + ((size_t)b * NN + i0) * DD + d0;
#pragma unroll
    for (int mt = 0; mt < 2; mt++) {
        const int r0 = wi * 32 + mt * 16 + g;
#pragma unroll
        for (int nt = 0; nt < 8; nt++) {
            const int c0 = wj * 64 + nt * 8 + tt * 2;
            *(float2*)&obase[(size_t)r0 * DD + c0]       = make_float2(acc[mt][nt][0], acc[mt][nt][1]);
            *(float2*)&obase[(size_t)(r0 + 8) * DD + c0] = make_float2(acc[mt][nt][2], acc[mt][nt][3]);
        }
    }
}

// ---------------------------------------------------------------------------
extern "C" void kernel_launch(void* const* d_in, const int* in_sizes, int n_in,
                              void* d_out, int out_size)
{
    const float* hidden = (const float*)d_in[0];
    const int*   adj    = (const int*)d_in[1];
    const float* a0     = (const float*)d_in[2];
    const float* a1     = (const float*)d_in[3];
    const float* a2     = (const float*)d_in[4];
    const float* a3     = (const float*)d_in[5];
    float* out = (float*)d_out;

    cudaFuncSetAttribute(k_scores_tc,
        cudaFuncAttributeMaxDynamicSharedMemorySize, S_SMEM_BYTES);
    cudaFuncSetAttribute(k_av_tc,
        cudaFuncAttributeMaxDynamicSharedMemorySize, V_SMEM_BYTES);

    k_split<<<(BB * NN * DD / 4) / 256, 256>>>(hidden, a0, a1, a2, a3);

    dim3 g1(NN / 128, 16, BB);
    k_scores_tc<<<g1, 256, S_SMEM_BYTES>>>(adj);

    k_softmax<<<(BB * NN) / 8, 256>>>();

    dim3 g3(DD / 128, NN / 128, BB);
    k_av_tc<<<g3, 256, V_SMEM_BYTES>>>(out);
}